// round 17
// baseline (speedup 1.0000x reference)
#include <cuda_runtime.h>
#include <cuda_bf16.h>
#include <cstdint>

#define NN 6144
#define IN_DIM 512
#define CHANNELS 4
#define C_DIM 64
#define FDIM 256          // CHANNELS * C_DIM
#define CAP 128           // max neighbors per row (mean ~31, sd ~5.5)
#define KPAIRS 256        // IN_DIM/2

// -------- scratch (device globals; no allocation allowed) --------
// Rows of g_feats are stored PERMUTED: canonical element e (owner lane
// l = e>>3, sub s = e&7) lives at float offset (s>=4)*128 + l*4 + (s&3).
// Row NN is a permanent all-zero row (sentinel target).
__device__ float g_featsA[(size_t)(NN + 1) * FDIM];
__device__ float g_featsB[(size_t)(NN + 1) * FDIM];
__device__ int   g_ell[(size_t)NN * CAP + 64];
__device__ int   g_deg[NN];
// pre-split bf16 hi/lo pairs (bit-identical to in-kernel split)
__device__ uint32_t g_Ah[(size_t)NN * KPAIRS];
__device__ uint32_t g_Al[(size_t)NN * KPAIRS];
__device__ uint32_t g_Wh[CHANNELS * KPAIRS * C_DIM];
__device__ uint32_t g_Wl[CHANNELS * KPAIRS * C_DIM];
// work-stealing counters, one per iterate pass (memset to 0 each launch)
__device__ unsigned int g_ctr[4];

// ============================================================
// Kernel 1: dense adj -> ELL (order-preserving, deterministic)
// warp/row, int4 + 4-ballot compaction, sentinel padding to x4.
// ============================================================
__global__ __launch_bounds__(256) void build_ell_kernel(const int* __restrict__ adj) {
    int row = blockIdx.x * 8 + (threadIdx.x >> 5);
    int lane = threadIdx.x & 31;
    const int4* arow = (const int4*)(adj + (size_t)row * NN);
    unsigned lt = (1u << lane) - 1u;
    int total = 0;
    int* erow = g_ell + (size_t)row * CAP;
    for (int it = 0; it < NN / 128; it++) {
        int4 v = arow[it * 32 + lane];
        bool p0 = v.x > 0, p1 = v.y > 0, p2 = v.z > 0, p3 = v.w > 0;
        unsigned b0 = __ballot_sync(0xffffffffu, p0);
        unsigned b1 = __ballot_sync(0xffffffffu, p1);
        unsigned b2 = __ballot_sync(0xffffffffu, p2);
        unsigned b3 = __ballot_sync(0xffffffffu, p3);
        int basec = __popc(b0 & lt) + __popc(b1 & lt) + __popc(b2 & lt) + __popc(b3 & lt);
        int idx0 = it * 128 + lane * 4;
        int pos = total + basec;
        if (p0) { if (pos < CAP) erow[pos] = idx0; pos++; }
        if (p1) { if (pos < CAP) erow[pos] = idx0 + 1; pos++; }
        if (p2) { if (pos < CAP) erow[pos] = idx0 + 2; pos++; }
        if (p3) { if (pos < CAP) erow[pos] = idx0 + 3; }
        total += __popc(b0) + __popc(b1) + __popc(b2) + __popc(b3);
    }
    int tc = total < CAP ? total : CAP;
    int pad = (tc + 3) & ~3;
    if (lane < pad - tc) erow[tc + lane] = NN;   // sentinel -> zero row
    if (lane == 0) g_deg[row] = pad;
}

// ============================================================
// bf16 hi/lo split helpers (shared by presplit; bit-exact)
// ============================================================
__device__ __forceinline__ uint32_t bfpair(float lo, float hi) {
    uint32_t r;
    asm("cvt.rn.bf16x2.f32 %0, %1, %2;" : "=r"(r) : "f"(hi), "f"(lo));
    return r;
}
__device__ __forceinline__ void split_pair(float e, float o, uint32_t& h, uint32_t& l) {
    h = bfpair(e, o);
    float he = __uint_as_float(h << 16);
    float ho = __uint_as_float(h & 0xffff0000u);
    l = bfpair(e - he, o - ho);
}

// ============================================================
// Kernel 1b: pre-split A (features) and W to bf16 hi/lo pairs.
// Blocks [0,1536): A — thread = (row, quad of 4 k-pairs).
// Blocks [1536,1600): W — thread = (c, kpair-row, 4 cols).
// ============================================================
__global__ __launch_bounds__(256) void presplit_kernel(const float* __restrict__ feat,
                                                       const float* __restrict__ W) {
    if (blockIdx.x < 1536) {
        int tid = blockIdx.x * 256 + threadIdx.x;   // 393216 = 6144*64
        int row = tid >> 6, quad = tid & 63;
        const float* fp = feat + (size_t)row * IN_DIM + quad * 8;
        float4 v0 = *(const float4*)fp;
        float4 v1 = *(const float4*)(fp + 4);
        uint32_t h0, h1, h2, h3, l0, l1, l2, l3;
        split_pair(v0.x, v0.y, h0, l0);
        split_pair(v0.z, v0.w, h1, l1);
        split_pair(v1.x, v1.y, h2, l2);
        split_pair(v1.z, v1.w, h3, l3);
        *(uint4*)&g_Ah[(size_t)row * KPAIRS + quad * 4] = make_uint4(h0, h1, h2, h3);
        *(uint4*)&g_Al[(size_t)row * KPAIRS + quad * 4] = make_uint4(l0, l1, l2, l3);
    } else {
        int tid = (blockIdx.x - 1536) * 256 + threadIdx.x;  // 16384 = 4*256*16
        int c = tid >> 12, r = tid & 4095;
        int kp = r >> 4, ng = r & 15;
        const float* wp = W + ((size_t)c * IN_DIM + 2 * kp) * C_DIM + ng * 4;
        float4 e = *(const float4*)wp;
        float4 o = *(const float4*)(wp + C_DIM);
        uint32_t h0, h1, h2, h3, l0, l1, l2, l3;
        split_pair(e.x, o.x, h0, l0);
        split_pair(e.y, o.y, h1, l1);
        split_pair(e.z, o.z, h2, l2);
        split_pair(e.w, o.w, h3, l3);
        *(uint4*)&g_Wh[((size_t)c * KPAIRS + kp) * C_DIM + ng * 4] = make_uint4(h0, h1, h2, h3);
        *(uint4*)&g_Wl[((size_t)c * KPAIRS + kp) * C_DIM + ng * 4] = make_uint4(l0, l1, l2, l3);
    }
}

// ============================================================
// Kernel 2: project via bf16 3-term split MMA (m16n8k16).
// R16 structure; staging is now pure LDG->STS copies of the
// pre-split pairs (no conversion math in the hot path).
// ============================================================
#define BMMA(C, A0, A1, A2, A3, B0, B1) \
    asm("mma.sync.aligned.m16n8k16.row.col.f32.bf16.bf16.f32 " \
        "{%0,%1,%2,%3}, {%4,%5,%6,%7}, {%8,%9}, {%0,%1,%2,%3};" \
        : "+f"(C[0]), "+f"(C[1]), "+f"(C[2]), "+f"(C[3]) \
        : "r"(A0), "r"(A1), "r"(A2), "r"(A3), "r"(B0), "r"(B1))

__global__ __launch_bounds__(128) void project_kernel(const float* __restrict__ bias) {
    __shared__ uint32_t sAh[32][20], sAl[32][20];   // [row][k-pair], pad 20
    __shared__ uint32_t sWh[16][72], sWl[16][72];   // [k-pair-row][n], pad 72
    __shared__ float spart[2][32];

    const int c  = blockIdx.y;
    const int n0 = blockIdx.x * 32;
    const int t  = threadIdx.x;
    const int w  = t >> 5, lane = t & 31;
    const int g  = lane >> 2, tq = lane & 3;
    const int rhalf = w & 1, chalf = w >> 1;
    const int r0 = rhalf * 16 + g;

    float acc[4][4];
#pragma unroll
    for (int nt = 0; nt < 4; nt++)
#pragma unroll
        for (int k = 0; k < 4; k++) acc[nt][k] = 0.f;

    const int arow = t >> 2, aseg = t & 3;          // A stage
    const int kp   = t >> 3, m = t & 7;             // W stage

    for (int d0 = 0; d0 < IN_DIM; d0 += 32) {
        const int kp0 = d0 >> 1;
        // A stage: pure copies
        {
            size_t src = (size_t)(n0 + arow) * KPAIRS + kp0 + aseg * 4;
            *(uint4*)&sAh[arow][aseg * 4] = *(const uint4*)&g_Ah[src];
            *(uint4*)&sAl[arow][aseg * 4] = *(const uint4*)&g_Al[src];
        }
        // W stage: pure copies
        {
            size_t src = ((size_t)c * KPAIRS + kp0 + kp) * C_DIM + m * 8;
            *(uint4*)&sWh[kp][m * 8]     = *(const uint4*)&g_Wh[src];
            *(uint4*)&sWh[kp][m * 8 + 4] = *(const uint4*)&g_Wh[src + 4];
            *(uint4*)&sWl[kp][m * 8]     = *(const uint4*)&g_Wl[src];
            *(uint4*)&sWl[kp][m * 8 + 4] = *(const uint4*)&g_Wl[src + 4];
        }
        __syncthreads();

#pragma unroll
        for (int s = 0; s < 2; s++) {
            const int kb = s * 8;
            uint32_t ah0 = sAh[r0][kb + tq];
            uint32_t ah1 = sAh[r0 + 8][kb + tq];
            uint32_t ah2 = sAh[r0][kb + tq + 4];
            uint32_t ah3 = sAh[r0 + 8][kb + tq + 4];
            uint32_t al0 = sAl[r0][kb + tq];
            uint32_t al1 = sAl[r0 + 8][kb + tq];
            uint32_t al2 = sAl[r0][kb + tq + 4];
            uint32_t al3 = sAl[r0 + 8][kb + tq + 4];
#pragma unroll
            for (int nt = 0; nt < 4; nt++) {
                const int nc = chalf * 32 + nt * 8 + g;
                uint32_t bh0 = sWh[kb + tq][nc];
                uint32_t bh1 = sWh[kb + tq + 4][nc];
                uint32_t bl0 = sWl[kb + tq][nc];
                uint32_t bl1 = sWl[kb + tq + 4][nc];
                BMMA(acc[nt], ah0, ah1, ah2, ah3, bh0, bh1);
                BMMA(acc[nt], ah0, ah1, ah2, ah3, bl0, bl1);
                BMMA(acc[nt], al0, al1, al2, al3, bh0, bh1);
            }
        }
        __syncthreads();
    }

    // epilogue: bias, cross-warp per-row L2 norm, permuted store
    float sos0 = 0.f, sos1 = 0.f;
#pragma unroll
    for (int nt = 0; nt < 4; nt++) {
        float2 bb = *(const float2*)(bias + c * C_DIM + chalf * 32 + nt * 8 + 2 * tq);
        acc[nt][0] += bb.x; acc[nt][1] += bb.y;
        acc[nt][2] += bb.x; acc[nt][3] += bb.y;
        sos0 += acc[nt][0] * acc[nt][0] + acc[nt][1] * acc[nt][1];
        sos1 += acc[nt][2] * acc[nt][2] + acc[nt][3] * acc[nt][3];
    }
    sos0 += __shfl_xor_sync(0xffffffffu, sos0, 1);
    sos0 += __shfl_xor_sync(0xffffffffu, sos0, 2);
    sos1 += __shfl_xor_sync(0xffffffffu, sos1, 1);
    sos1 += __shfl_xor_sync(0xffffffffu, sos1, 2);
    if (tq == 0) {
        spart[chalf][r0] = sos0;
        spart[chalf][r0 + 8] = sos1;
    }
    __syncthreads();
    float sc0 = rsqrtf(fmaxf(spart[0][r0] + spart[1][r0], 1e-24f));
    float sc1 = rsqrtf(fmaxf(spart[0][r0 + 8] + spart[1][r0 + 8], 1e-24f));

    const int off = (tq >= 2 ? 128 : 0) + ((2 * tq) & 3);
#pragma unroll
    for (int nt = 0; nt < 4; nt++) {
        int pp = (c * 8 + chalf * 4 + nt) * 4 + off;
        *(float2*)(g_featsA + (size_t)(n0 + r0) * FDIM + pp) =
            make_float2(acc[nt][0] * sc0, acc[nt][1] * sc0);
        *(float2*)(g_featsA + (size_t)(n0 + r0 + 8) * FDIM + pp) =
            make_float2(acc[nt][2] * sc1, acc[nt][3] * sc1);
    }
}

// ============================================================
// Kernel 3: PERSISTENT iterate with atomic work-stealing.
// Grid = 1036 (all-resident); each warp pulls node ids from
// g_ctr[pass] with next-id prefetch (atomic latency hidden).
// Node body = proven R13 loop (permuted layout, 4-way ILP,
// 5 shfls/edge). Output deterministic (per-node independent).
// ============================================================
__global__ __launch_bounds__(128) void iterate_kernel(int pass, float* __restrict__ d_final) {
    const float* __restrict__ src = (pass == 1) ? g_featsB : g_featsA;
    float* __restrict__ dst = (pass == 0) ? g_featsB : (pass == 1) ? g_featsA : d_final;

    const int lane = threadIdx.x & 31;

    unsigned idx = 0;
    if (lane == 0) idx = atomicAdd(&g_ctr[pass], 1u);
    idx = __shfl_sync(0xffffffffu, idx, 0);

    while (idx < NN) {
        unsigned nxt = 0;
        if (lane == 0) nxt = atomicAdd(&g_ctr[pass], 1u);   // prefetch next id

        const int n = (int)idx;
        const float* xrow = src + (size_t)n * FDIM + lane * 4;
        float4 x0 = *(const float4*)xrow;
        float4 x1 = *(const float4*)(xrow + 128);
        float4 a0 = make_float4(0.f, 0.f, 0.f, 0.f);
        float4 a1 = make_float4(0.f, 0.f, 0.f, 0.f);

        const int dp = g_deg[n];
        const int* erow = g_ell + (size_t)n * CAP;

        for (int i = 0; i < dp; i += 4) {
            int col[4];
#pragma unroll
            for (int j = 0; j < 4; j++) col[j] = __ldg(erow + i + j);

            float4 y0[4], y1[4];
#pragma unroll
            for (int j = 0; j < 4; j++) {
                const float* yr = src + (size_t)col[j] * FDIM + lane * 4;
                y0[j] = *(const float4*)yr;
                y1[j] = *(const float4*)(yr + 128);
            }

            float p[4];
#pragma unroll
            for (int j = 0; j < 4; j++)
                p[j] = x0.x * y0[j].x + x0.y * y0[j].y + x0.z * y0[j].z + x0.w * y0[j].w +
                       x1.x * y1[j].x + x1.y * y1[j].y + x1.z * y1[j].z + x1.w * y1[j].w;
#pragma unroll
            for (int j = 0; j < 4; j++) p[j] += __shfl_xor_sync(0xffffffffu, p[j], 1);
#pragma unroll
            for (int j = 0; j < 4; j++) p[j] += __shfl_xor_sync(0xffffffffu, p[j], 2);
#pragma unroll
            for (int j = 0; j < 4; j++) p[j] += __shfl_xor_sync(0xffffffffu, p[j], 4);
            float e[4], t[4];
#pragma unroll
            for (int j = 0; j < 4; j++) e[j] = __expf(p[j]);
#pragma unroll
            for (int j = 0; j < 4; j++) t[j] = e[j] + __shfl_xor_sync(0xffffffffu, e[j], 8);
#pragma unroll
            for (int j = 0; j < 4; j++) t[j] += __shfl_xor_sync(0xffffffffu, t[j], 16);
#pragma unroll
            for (int j = 0; j < 4; j++) {
                float wgt = __fdividef(e[j], t[j]);
                a0.x += wgt * y0[j].x; a0.y += wgt * y0[j].y;
                a0.z += wgt * y0[j].z; a0.w += wgt * y0[j].w;
                a1.x += wgt * y1[j].x; a1.y += wgt * y1[j].y;
                a1.z += wgt * y1[j].z; a1.w += wgt * y1[j].w;
            }
        }

        float v[8];
        v[0] = x0.x + a0.x; v[1] = x0.y + a0.y; v[2] = x0.z + a0.z; v[3] = x0.w + a0.w;
        v[4] = x1.x + a1.x; v[5] = x1.y + a1.y; v[6] = x1.z + a1.z; v[7] = x1.w + a1.w;
        float sq = 0.f;
#pragma unroll
        for (int k = 0; k < 8; k++) sq += v[k] * v[k];
        sq += __shfl_xor_sync(0xffffffffu, sq, 1);
        sq += __shfl_xor_sync(0xffffffffu, sq, 2);
        sq += __shfl_xor_sync(0xffffffffu, sq, 4);
        float sc = rsqrtf(fmaxf(sq, 1e-24f));
        if (pass == 2) {
            float* drow = dst + (size_t)n * FDIM + lane * 8;
            *(float4*)drow       = make_float4(v[0] * sc, v[1] * sc, v[2] * sc, v[3] * sc);
            *(float4*)(drow + 4) = make_float4(v[4] * sc, v[5] * sc, v[6] * sc, v[7] * sc);
        } else {
            float* drow = dst + (size_t)n * FDIM + lane * 4;
            *(float4*)drow         = make_float4(v[0] * sc, v[1] * sc, v[2] * sc, v[3] * sc);
            *(float4*)(drow + 128) = make_float4(v[4] * sc, v[5] * sc, v[6] * sc, v[7] * sc);
        }

        idx = __shfl_sync(0xffffffffu, nxt, 0);
    }
}

// ============================================================
extern "C" void kernel_launch(void* const* d_in, const int* in_sizes, int n_in,
                              void* d_out, int out_size) {
    const float* features = (const float*)d_in[0];   // [6144, 512]
    const int*   adj      = (const int*)d_in[1];     // [6144, 6144]
    const float* W        = (const float*)d_in[2];   // [4, 512, 64]
    const float* b        = (const float*)d_in[3];   // [4, 1, 64]
    float* out = (float*)d_out;                      // [6144, 256]

    void* ctr_addr = nullptr;
    cudaGetSymbolAddress(&ctr_addr, g_ctr);
    cudaMemsetAsync(ctr_addr, 0, 4 * sizeof(unsigned int));

    build_ell_kernel<<<NN / 8, 256>>>(adj);
    presplit_kernel<<<1600, 256>>>(features, W);
    project_kernel<<<dim3(NN / 32, CHANNELS), 128>>>(b);
    iterate_kernel<<<1036, 128>>>(0, out);
    iterate_kernel<<<1036, 128>>>(1, out);
    iterate_kernel<<<1036, 128>>>(2, out);
}